// round 1
// baseline (speedup 1.0000x reference)
#include <cuda_runtime.h>
#include <cstddef>

#define BATCH 8
#define SEQ   2048
#define DIM   768
#define MTOT  (BATCH*SEQ)   // 16384

// Scratch for projected Q and K (no dynamic allocation allowed).
__device__ float g_Q[(size_t)BATCH*SEQ*DIM];
__device__ float g_K[(size_t)BATCH*SEQ*DIM];

// ---------------------------------------------------------------------------
// Phase 1: Out[m,n] = sum_k X[m,k] * W[k,n] + bias[n]
// M = 16384, N = 768, K = 768. Tiles: BM=128, BN=64, BK=32. 256 threads, 8x4 micro.
// ---------------------------------------------------------------------------
#define BM 128
#define BN 64
#define BKG 32

__global__ void __launch_bounds__(256) gemm_bias_kernel(
    const float* __restrict__ X, const float* __restrict__ W,
    const float* __restrict__ bias, float* __restrict__ Out)
{
    __shared__ float As[BKG][BM + 4];   // transposed: As[k][m]
    __shared__ float Bs[BKG][BN];       // Bs[k][n]

    const int tid = threadIdx.x;
    const int tx  = tid & 15;   // n direction (16 * 4 = 64)
    const int ty  = tid >> 4;   // m direction (16 * 8 = 128)
    const int m0  = blockIdx.y * BM;
    const int n0  = blockIdx.x * BN;

    float acc[8][4];
#pragma unroll
    for (int i = 0; i < 8; i++)
#pragma unroll
        for (int j = 0; j < 4; j++) acc[i][j] = 0.f;

    const int la_r = tid >> 3;          // 0..31 (row within a 32-row pass)
    const int la_c = (tid & 7) * 4;     // k column (float4)
    const int lb_r = tid >> 4;          // 0..15 (k row within 16-row pass)
    const int lb_c = (tid & 15) * 4;    // n column (float4)

    for (int k0 = 0; k0 < DIM; k0 += BKG) {
        // Load A tile 128x32, store transposed [k][m]
#pragma unroll
        for (int p = 0; p < 4; p++) {
            const int m = la_r + p * 32;
            float4 v = *(const float4*)&X[(size_t)(m0 + m) * DIM + k0 + la_c];
            As[la_c + 0][m] = v.x; As[la_c + 1][m] = v.y;
            As[la_c + 2][m] = v.z; As[la_c + 3][m] = v.w;
        }
        // Load B tile 32x64 (natural layout)
#pragma unroll
        for (int p = 0; p < 2; p++) {
            const int kr = lb_r + p * 16;
            *(float4*)&Bs[kr][lb_c] =
                *(const float4*)&W[(size_t)(k0 + kr) * DIM + n0 + lb_c];
        }
        __syncthreads();

#pragma unroll
        for (int kk = 0; kk < BKG; kk++) {
            float4 a0 = *(const float4*)&As[kk][ty * 8];
            float4 a1 = *(const float4*)&As[kk][ty * 8 + 4];
            float4 b0 = *(const float4*)&Bs[kk][tx * 4];
            float a[8] = {a0.x, a0.y, a0.z, a0.w, a1.x, a1.y, a1.z, a1.w};
            float bb[4] = {b0.x, b0.y, b0.z, b0.w};
#pragma unroll
            for (int i = 0; i < 8; i++)
#pragma unroll
                for (int j = 0; j < 4; j++) acc[i][j] += a[i] * bb[j];
        }
        __syncthreads();
    }

    // Epilogue: + bias, store
    float4 bv = *(const float4*)&bias[n0 + tx * 4];
#pragma unroll
    for (int i = 0; i < 8; i++) {
        const int m = m0 + ty * 8 + i;
        float4 o;
        o.x = acc[i][0] + bv.x; o.y = acc[i][1] + bv.y;
        o.z = acc[i][2] + bv.z; o.w = acc[i][3] + bv.w;
        *(float4*)&Out[(size_t)m * DIM + n0 + tx * 4] = o;
    }
}

// ---------------------------------------------------------------------------
// Phase 2: for each (b, t):
//   out[b,t] = (sum_s e(qk)*qk) / (sum_s e(qk) + 1e-7),  e(x)=exp(tanh(x)),
//   qk = Q[b,s,:] . K[b,t,:]
// Block: one 32-wide t-strip of one batch; loops over all s in 128-row tiles.
// 256 threads, micro-tile 8(s) x 2(t). Shared-atomic num/den accumulation.
// ---------------------------------------------------------------------------
#define TBS 128
#define TBT 32
#define TBK 32

__device__ __forceinline__ float fast_tanh(float x) {
    float y;
    asm("tanh.approx.f32 %0, %1;" : "=f"(y) : "f"(x));
    return y;
}

__global__ void __launch_bounds__(256) attn_reduce_kernel(
    const float* __restrict__ Q, const float* __restrict__ K,
    float* __restrict__ out)
{
    __shared__ float Qs[TBK][TBS + 4];   // [k][s]
    __shared__ float Ks[TBK][TBT + 4];   // [k][t]
    __shared__ float num_sh[TBT];
    __shared__ float den_sh[TBT];

    const int tid = threadIdx.x;
    const int tx  = tid & 15;    // t direction: 2 values each
    const int ty  = tid >> 4;    // s direction: 8 values each
    const int b   = blockIdx.y;
    const int t0  = blockIdx.x * TBT;

    const float* __restrict__ Qb = Q + (size_t)b * SEQ * DIM;
    const float* __restrict__ Kb = K + (size_t)b * SEQ * DIM;

    if (tid < TBT) { num_sh[tid] = 0.f; den_sh[tid] = 0.f; }

    const int qa_r = tid >> 3;        // 0..31
    const int qa_c = (tid & 7) * 4;   // k column
    const int ka_r = tid >> 3;        // 0..31 t-row
    const int ka_c = (tid & 7) * 4;

    for (int s0 = 0; s0 < SEQ; s0 += TBS) {
        float acc[8][2];
#pragma unroll
        for (int i = 0; i < 8; i++) { acc[i][0] = 0.f; acc[i][1] = 0.f; }

        for (int k0 = 0; k0 < DIM; k0 += TBK) {
            // Q tile 128x32 -> transposed
#pragma unroll
            for (int p = 0; p < 4; p++) {
                const int s = qa_r + p * 32;
                float4 v = *(const float4*)&Qb[(size_t)(s0 + s) * DIM + k0 + qa_c];
                Qs[qa_c + 0][s] = v.x; Qs[qa_c + 1][s] = v.y;
                Qs[qa_c + 2][s] = v.z; Qs[qa_c + 3][s] = v.w;
            }
            // K tile 32x32 -> transposed
            {
                float4 v = *(const float4*)&Kb[(size_t)(t0 + ka_r) * DIM + k0 + ka_c];
                Ks[ka_c + 0][ka_r] = v.x; Ks[ka_c + 1][ka_r] = v.y;
                Ks[ka_c + 2][ka_r] = v.z; Ks[ka_c + 3][ka_r] = v.w;
            }
            __syncthreads();

#pragma unroll
            for (int kk = 0; kk < TBK; kk++) {
                float4 a0 = *(const float4*)&Qs[kk][ty * 8];
                float4 a1 = *(const float4*)&Qs[kk][ty * 8 + 4];
                float2 bb = *(const float2*)&Ks[kk][tx * 2];
                float a[8] = {a0.x, a0.y, a0.z, a0.w, a1.x, a1.y, a1.z, a1.w};
#pragma unroll
                for (int i = 0; i < 8; i++) {
                    acc[i][0] += a[i] * bb.x;
                    acc[i][1] += a[i] * bb.y;
                }
            }
            __syncthreads();
        }

        // Fused epilogue for this s-tile: e = exp(tanh(qk)); num += e*qk; den += e
        float nloc0 = 0.f, nloc1 = 0.f, dloc0 = 0.f, dloc1 = 0.f;
#pragma unroll
        for (int i = 0; i < 8; i++) {
            float q0 = acc[i][0];
            float q1 = acc[i][1];
            float e0 = __expf(fast_tanh(q0));
            float e1 = __expf(fast_tanh(q1));
            nloc0 += e0 * q0; dloc0 += e0;
            nloc1 += e1 * q1; dloc1 += e1;
        }
        atomicAdd(&num_sh[tx * 2 + 0], nloc0);
        atomicAdd(&num_sh[tx * 2 + 1], nloc1);
        atomicAdd(&den_sh[tx * 2 + 0], dloc0);
        atomicAdd(&den_sh[tx * 2 + 1], dloc1);
    }
    __syncthreads();

    if (tid < TBT) {
        out[(size_t)b * SEQ + t0 + tid] = num_sh[tid] / (den_sh[tid] + 1e-7f);
    }
}

// ---------------------------------------------------------------------------
extern "C" void kernel_launch(void* const* d_in, const int* in_sizes, int n_in,
                              void* d_out, int out_size)
{
    const float* x1 = (const float*)d_in[0];
    const float* x2 = (const float*)d_in[1];
    const float* Wq = (const float*)d_in[2];
    const float* bq = (const float*)d_in[3];
    const float* Wk = (const float*)d_in[4];
    const float* bk = (const float*)d_in[5];
    float* out = (float*)d_out;

    float *Qp = nullptr, *Kp = nullptr;
    cudaGetSymbolAddress((void**)&Qp, g_Q);
    cudaGetSymbolAddress((void**)&Kp, g_K);

    dim3 gridGemm(DIM / BN, MTOT / BM);   // (12, 128)
    gemm_bias_kernel<<<gridGemm, 256>>>(x1, Wq, bq, Qp);
    gemm_bias_kernel<<<gridGemm, 256>>>(x2, Wk, bk, Kp);

    dim3 gridAttn(SEQ / TBT, BATCH);      // (64, 8)
    attn_reduce_kernel<<<gridAttn, 256>>>(Qp, Kp, out);
}

// round 3
// speedup vs baseline: 6.5576x; 6.5576x over previous
#include <cuda_runtime.h>
#include <cuda_bf16.h>
#include <cstdint>
#include <cstddef>

#define BATCH 8
#define SEQ   2048
#define DIM   768
#define MTOT  (BATCH*SEQ)   // 16384

// ---------------- scratch (no dynamic allocation allowed) -------------------
__device__ __nv_bfloat16 g_X1b[(size_t)MTOT*DIM];
__device__ __nv_bfloat16 g_X2b[(size_t)MTOT*DIM];
__device__ __nv_bfloat16 g_Q  [(size_t)MTOT*DIM];
__device__ __nv_bfloat16 g_K  [(size_t)MTOT*DIM];
__device__ __nv_bfloat16 g_Wqt[(size_t)DIM*DIM];
__device__ __nv_bfloat16 g_Wkt[(size_t)DIM*DIM];
__device__ float g_num[MTOT / DIM * 0 + BATCH*SEQ];   // 16384
__device__ float g_den[BATCH*SEQ];

// ---------------- helpers ----------------------------------------------------
__device__ __forceinline__ uint32_t smem_u32(const void* p) {
    uint32_t a;
    asm("{ .reg .u64 t; cvta.to.shared.u64 t, %1; cvt.u32.u64 %0, t; }"
        : "=r"(a) : "l"(p));
    return a;
}
__device__ __forceinline__ void ldsm_x4(uint32_t* r, uint32_t addr) {
    asm volatile("ldmatrix.sync.aligned.m8n8.x4.shared.b16 {%0,%1,%2,%3}, [%4];"
                 : "=r"(r[0]), "=r"(r[1]), "=r"(r[2]), "=r"(r[3]) : "r"(addr));
}
__device__ __forceinline__ void mma_bf16(float* c, const uint32_t* a,
                                         uint32_t b0, uint32_t b1) {
    asm volatile(
        "mma.sync.aligned.m16n8k16.row.col.f32.bf16.bf16.f32 "
        "{%0,%1,%2,%3}, {%4,%5,%6,%7}, {%8,%9}, {%0,%1,%2,%3};"
        : "+f"(c[0]), "+f"(c[1]), "+f"(c[2]), "+f"(c[3])
        : "r"(a[0]), "r"(a[1]), "r"(a[2]), "r"(a[3]), "r"(b0), "r"(b1));
}
__device__ __forceinline__ float fast_tanh(float x) {
    float y; asm("tanh.approx.f32 %0, %1;" : "=f"(y) : "f"(x)); return y;
}

// SMEM tile: 128 rows x 32 bf16, padded to 80 bytes/row (conflict-free ldmatrix)
#define SROW  80
#define TILEB (128*SROW)       // 10240 bytes
#define OFF_A0 0
#define OFF_A1 TILEB
#define OFF_B0 (2*TILEB)
#define OFF_B1 (3*TILEB)
#define NCHUNK 24              // 768 / 32

// ---------------------------------------------------------------------------
// small elementwise kernels
// ---------------------------------------------------------------------------
__global__ void convert_bf16(const float* __restrict__ x, __nv_bfloat16* __restrict__ y)
{
    const size_t i = ((size_t)blockIdx.x * blockDim.x + threadIdx.x) * 4;
    float4 v = *(const float4*)(x + i);
    __nv_bfloat162 lo = __floats2bfloat162_rn(v.x, v.y);
    __nv_bfloat162 hi = __floats2bfloat162_rn(v.z, v.w);
    uint2 st; st.x = *(uint32_t*)&lo; st.y = *(uint32_t*)&hi;
    *(uint2*)(y + i) = st;
}

__global__ void transpose_bf16(const float* __restrict__ W, __nv_bfloat16* __restrict__ Wt)
{
    __shared__ float t[32][33];
    int tx = threadIdx.x, ty = threadIdx.y;
    int bk = blockIdx.y * 32, bn = blockIdx.x * 32;
#pragma unroll
    for (int j = 0; j < 4; j++)
        t[ty + j * 8][tx] = W[(size_t)(bk + ty + j * 8) * DIM + bn + tx];
    __syncthreads();
#pragma unroll
    for (int j = 0; j < 4; j++)
        Wt[(size_t)(bn + ty + j * 8) * DIM + bk + tx] = __float2bfloat16(t[tx][ty + j * 8]);
}

__global__ void init_accum(float* __restrict__ n, float* __restrict__ d)
{
    const int i = blockIdx.x * blockDim.x + threadIdx.x;
    n[i] = 0.f; d[i] = 0.f;
}

__global__ void finalize(const float* __restrict__ n, const float* __restrict__ d,
                         float* __restrict__ out)
{
    const int i = blockIdx.x * blockDim.x + threadIdx.x;
    out[i] = n[i] / (d[i] + 1e-7f);
}

// ---------------------------------------------------------------------------
// Phase 1: Out[m,n] = bf16( sum_k A[m,k]*Bt[n,k] + bias[n] )
// CTA tile 128x128, K chunks of 32 (double-buffered SMEM), 8 warps (4m x 2n),
// warp tile 32x64 via mma.sync m16n8k16 bf16.
// ---------------------------------------------------------------------------
__global__ void __launch_bounds__(256, 2)
gemm_bias_mma(const __nv_bfloat16* __restrict__ A, const __nv_bfloat16* __restrict__ Bt,
              const float* __restrict__ bias, __nv_bfloat16* __restrict__ Out)
{
    __shared__ __align__(16) char smem[4*TILEB + 512];
    const uint32_t sb = smem_u32(smem);
    const int tid = threadIdx.x, lane = tid & 31, wid = tid >> 5;
    const int wm = wid >> 1, wn = wid & 1;
    const int n0 = blockIdx.x * 128, m0 = blockIdx.y * 128;

    float* bias_s = (float*)(smem + 4*TILEB);
    if (tid < 128) bias_s[tid] = bias[n0 + tid];

    const __nv_bfloat16* Ag = A  + (size_t)m0 * DIM;
    const __nv_bfloat16* Bg = Bt + (size_t)n0 * DIM;
    const int lr = tid >> 2;          // 0..63
    const int ls = tid & 3;           // 16B segment

    float acc[2][8][4];
#pragma unroll
    for (int i = 0; i < 2; i++)
#pragma unroll
        for (int j = 0; j < 8; j++)
#pragma unroll
            for (int q = 0; q < 4; q++) acc[i][j][q] = 0.f;

    // preload chunk 0
    {
        uint4 va0 = *(const uint4*)(Ag + (size_t)lr        * DIM + ls * 8);
        uint4 va1 = *(const uint4*)(Ag + (size_t)(lr + 64) * DIM + ls * 8);
        uint4 vb0 = *(const uint4*)(Bg + (size_t)lr        * DIM + ls * 8);
        uint4 vb1 = *(const uint4*)(Bg + (size_t)(lr + 64) * DIM + ls * 8);
        *(uint4*)(smem + OFF_A0 + lr        * SROW + ls * 16) = va0;
        *(uint4*)(smem + OFF_A0 + (lr + 64) * SROW + ls * 16) = va1;
        *(uint4*)(smem + OFF_B0 + lr        * SROW + ls * 16) = vb0;
        *(uint4*)(smem + OFF_B0 + (lr + 64) * SROW + ls * 16) = vb1;
    }
    __syncthreads();

    const uint32_t lane_off = (uint32_t)(lane & 15) * SROW + (uint32_t)(lane >> 4) * 16;

    for (int c = 0; c < NCHUNK; c++) {
        const uint32_t As = sb + ((c & 1) ? OFF_A1 : OFF_A0);
        const uint32_t Bs = sb + ((c & 1) ? OFF_B1 : OFF_B0);
        uint4 va0, va1, vb0, vb1;
        if (c < NCHUNK - 1) {
            const int ko = (c + 1) * 32;
            va0 = *(const uint4*)(Ag + (size_t)lr        * DIM + ko + ls * 8);
            va1 = *(const uint4*)(Ag + (size_t)(lr + 64) * DIM + ko + ls * 8);
            vb0 = *(const uint4*)(Bg + (size_t)lr        * DIM + ko + ls * 8);
            vb1 = *(const uint4*)(Bg + (size_t)(lr + 64) * DIM + ko + ls * 8);
        }
#pragma unroll
        for (int ks = 0; ks < 2; ks++) {
            uint32_t a0[4], a1[4];
            ldsm_x4(a0, As + (uint32_t)(wm * 32)      * SROW + ks * 32 + lane_off);
            ldsm_x4(a1, As + (uint32_t)(wm * 32 + 16) * SROW + ks * 32 + lane_off);
#pragma unroll
            for (int np = 0; np < 4; np++) {
                uint32_t bm[4];
                ldsm_x4(bm, Bs + (uint32_t)(wn * 64 + np * 16) * SROW + ks * 32 + lane_off);
                mma_bf16(acc[0][np*2],   a0, bm[0], bm[2]);
                mma_bf16(acc[0][np*2+1], a0, bm[1], bm[3]);
                mma_bf16(acc[1][np*2],   a1, bm[0], bm[2]);
                mma_bf16(acc[1][np*2+1], a1, bm[1], bm[3]);
            }
        }
        if (c < NCHUNK - 1) {
            char* An = smem + ((c & 1) ? OFF_A0 : OFF_A1);
            char* Bn = smem + ((c & 1) ? OFF_B0 : OFF_B1);
            *(uint4*)(An + lr        * SROW + ls * 16) = va0;
            *(uint4*)(An + (lr + 64) * SROW + ls * 16) = va1;
            *(uint4*)(Bn + lr        * SROW + ls * 16) = vb0;
            *(uint4*)(Bn + (lr + 64) * SROW + ls * 16) = vb1;
        }
        __syncthreads();
    }

    // epilogue: + bias, bf16 store
#pragma unroll
    for (int mt = 0; mt < 2; mt++) {
        const int m = m0 + wm * 32 + mt * 16 + (lane >> 2);
#pragma unroll
        for (int nt = 0; nt < 8; nt++) {
            const int nl = wn * 64 + nt * 8 + (lane & 3) * 2;
            const float b0 = bias_s[nl], b1 = bias_s[nl + 1];
            __nv_bfloat162 p0 = __floats2bfloat162_rn(acc[mt][nt][0] + b0, acc[mt][nt][1] + b1);
            __nv_bfloat162 p1 = __floats2bfloat162_rn(acc[mt][nt][2] + b0, acc[mt][nt][3] + b1);
            *(__nv_bfloat162*)(Out + (size_t)m       * DIM + n0 + nl) = p0;
            *(__nv_bfloat162*)(Out + (size_t)(m + 8) * DIM + n0 + nl) = p1;
        }
    }
}

// ---------------------------------------------------------------------------
// Phase 2: per (t-block 128, batch, s-half 1024):
//   for each s-tile of 128:  qk[s,t] = Q[s,:].K[t,:]  (same mma mainloop)
//   epilogue: e = exp(tanh(qk)); num[t] += e*qk; den[t] += e  (reduce over s)
// smem atomics per tile, global atomics across the 2 s-halves.
// ---------------------------------------------------------------------------
__global__ void __launch_bounds__(256, 2)
attn_mma(const __nv_bfloat16* __restrict__ Q, const __nv_bfloat16* __restrict__ K,
         float* __restrict__ gnum, float* __restrict__ gden)
{
    __shared__ __align__(16) char smem[4*TILEB + 1024];
    const uint32_t sb = smem_u32(smem);
    float* num_sh = (float*)(smem + 4*TILEB);
    float* den_sh = num_sh + 128;

    const int tid = threadIdx.x, lane = tid & 31, wid = tid >> 5;
    const int wm = wid >> 1, wn = wid & 1;
    const int t0 = blockIdx.x * 128, b = blockIdx.y, sh = blockIdx.z;

    if (tid < 128) { num_sh[tid] = 0.f; den_sh[tid] = 0.f; }

    const __nv_bfloat16* Kg    = K + ((size_t)b * SEQ + t0) * DIM;
    const __nv_bfloat16* Qbase = Q + ((size_t)b * SEQ + sh * 1024) * DIM;
    const int lr = tid >> 2, ls = tid & 3;
    const uint32_t lane_off = (uint32_t)(lane & 15) * SROW + (uint32_t)(lane >> 4) * 16;

    __syncthreads();

    for (int st = 0; st < 8; st++) {
        const __nv_bfloat16* Ag = Qbase + (size_t)(st * 128) * DIM;

        float acc[2][8][4];
#pragma unroll
        for (int i = 0; i < 2; i++)
#pragma unroll
            for (int j = 0; j < 8; j++)
#pragma unroll
                for (int q = 0; q < 4; q++) acc[i][j][q] = 0.f;

        // preload chunk 0
        {
            uint4 va0 = *(const uint4*)(Ag + (size_t)lr        * DIM + ls * 8);
            uint4 va1 = *(const uint4*)(Ag + (size_t)(lr + 64) * DIM + ls * 8);
            uint4 vb0 = *(const uint4*)(Kg + (size_t)lr        * DIM + ls * 8);
            uint4 vb1 = *(const uint4*)(Kg + (size_t)(lr + 64) * DIM + ls * 8);
            *(uint4*)(smem + OFF_A0 + lr        * SROW + ls * 16) = va0;
            *(uint4*)(smem + OFF_A0 + (lr + 64) * SROW + ls * 16) = va1;
            *(uint4*)(smem + OFF_B0 + lr        * SROW + ls * 16) = vb0;
            *(uint4*)(smem + OFF_B0 + (lr + 64) * SROW + ls * 16) = vb1;
        }
        __syncthreads();

        for (int c = 0; c < NCHUNK; c++) {
            const uint32_t As = sb + ((c & 1) ? OFF_A1 : OFF_A0);
            const uint32_t Bs = sb + ((c & 1) ? OFF_B1 : OFF_B0);
            uint4 va0, va1, vb0, vb1;
            if (c < NCHUNK - 1) {
                const int ko = (c + 1) * 32;
                va0 = *(const uint4*)(Ag + (size_t)lr        * DIM + ko + ls * 8);
                va1 = *(const uint4*)(Ag + (size_t)(lr + 64) * DIM + ko + ls * 8);
                vb0 = *(const uint4*)(Kg + (size_t)lr        * DIM + ko + ls * 8);
                vb1 = *(const uint4*)(Kg + (size_t)(lr + 64) * DIM + ko + ls * 8);
            }
#pragma unroll
            for (int ks = 0; ks < 2; ks++) {
                uint32_t a0[4], a1[4];
                ldsm_x4(a0, As + (uint32_t)(wm * 32)      * SROW + ks * 32 + lane_off);
                ldsm_x4(a1, As + (uint32_t)(wm * 32 + 16) * SROW + ks * 32 + lane_off);
#pragma unroll
                for (int np = 0; np < 4; np++) {
                    uint32_t bm[4];
                    ldsm_x4(bm, Bs + (uint32_t)(wn * 64 + np * 16) * SROW + ks * 32 + lane_off);
                    mma_bf16(acc[0][np*2],   a0, bm[0], bm[2]);
                    mma_bf16(acc[0][np*2+1], a0, bm[1], bm[3]);
                    mma_bf16(acc[1][np*2],   a1, bm[0], bm[2]);
                    mma_bf16(acc[1][np*2+1], a1, bm[1], bm[3]);
                }
            }
            if (c < NCHUNK - 1) {
                char* An = smem + ((c & 1) ? OFF_A0 : OFF_A1);
                char* Bn = smem + ((c & 1) ? OFF_B0 : OFF_B1);
                *(uint4*)(An + lr        * SROW + ls * 16) = va0;
                *(uint4*)(An + (lr + 64) * SROW + ls * 16) = va1;
                *(uint4*)(Bn + lr        * SROW + ls * 16) = vb0;
                *(uint4*)(Bn + (lr + 64) * SROW + ls * 16) = vb1;
            }
            __syncthreads();
        }

        // epilogue for this s-tile: reduce over s (rows) into num/den per t (col)
#pragma unroll
        for (int nt = 0; nt < 8; nt++) {
            float vn0 = 0.f, vn1 = 0.f, vd0 = 0.f, vd1 = 0.f;
#pragma unroll
            for (int mt = 0; mt < 2; mt++) {
                const float q0 = acc[mt][nt][0], q1 = acc[mt][nt][1];
                const float q2 = acc[mt][nt][2], q3 = acc[mt][nt][3];
                const float e0 = __expf(fast_tanh(q0));
                const float e1 = __expf(fast_tanh(q1));
                const float e2 = __expf(fast_tanh(q2));
                const float e3 = __expf(fast_tanh(q3));
                vn0 += e0 * q0 + e2 * q2;  vd0 += e0 + e2;
                vn1 += e1 * q1 + e3 * q3;  vd1 += e1 + e3;
            }
#pragma unroll
            for (int o = 4; o <= 16; o <<= 1) {
                vn0 += __shfl_xor_sync(0xFFFFFFFFu, vn0, o);
                vn1 += __shfl_xor_sync(0xFFFFFFFFu, vn1, o);
                vd0 += __shfl_xor_sync(0xFFFFFFFFu, vd0, o);
                vd1 += __shfl_xor_sync(0xFFFFFFFFu, vd1, o);
            }
            if (lane < 4) {
                const int col = wn * 64 + nt * 8 + lane * 2;
                atomicAdd(&num_sh[col],     vn0);
                atomicAdd(&num_sh[col + 1], vn1);
                atomicAdd(&den_sh[col],     vd0);
                atomicAdd(&den_sh[col + 1], vd1);
            }
        }
    }
    __syncthreads();
    if (tid < 128) {
        atomicAdd(&gnum[(size_t)b * SEQ + t0 + tid], num_sh[tid]);
        atomicAdd(&gden[(size_t)b * SEQ + t0 + tid], den_sh[tid]);
    }
}

// ---------------------------------------------------------------------------
extern "C" void kernel_launch(void* const* d_in, const int* in_sizes, int n_in,
                              void* d_out, int out_size)
{
    const float* x1 = (const float*)d_in[0];
    const float* x2 = (const float*)d_in[1];
    const float* Wq = (const float*)d_in[2];
    const float* bq = (const float*)d_in[3];
    const float* Wk = (const float*)d_in[4];
    const float* bk = (const float*)d_in[5];
    float* out = (float*)d_out;

    __nv_bfloat16 *X1b, *X2b, *Qp, *Kp, *Wqt, *Wkt;
    float *gnum, *gden;
    cudaGetSymbolAddress((void**)&X1b, g_X1b);
    cudaGetSymbolAddress((void**)&X2b, g_X2b);
    cudaGetSymbolAddress((void**)&Qp,  g_Q);
    cudaGetSymbolAddress((void**)&Kp,  g_K);
    cudaGetSymbolAddress((void**)&Wqt, g_Wqt);
    cudaGetSymbolAddress((void**)&Wkt, g_Wkt);
    cudaGetSymbolAddress((void**)&gnum, g_num);
    cudaGetSymbolAddress((void**)&gden, g_den);

    init_accum<<<BATCH*SEQ/256, 256>>>(gnum, gden);

    const int nconv = (int)(((size_t)MTOT * DIM / 4) / 256);   // 12288 blocks
    convert_bf16<<<nconv, 256>>>(x1, X1b);
    convert_bf16<<<nconv, 256>>>(x2, X2b);

    dim3 tgrid(DIM / 32, DIM / 32);
    transpose_bf16<<<tgrid, dim3(32, 8)>>>(Wq, Wqt);
    transpose_bf16<<<tgrid, dim3(32, 8)>>>(Wk, Wkt);

    dim3 ggrid(DIM / 128, MTOT / 128);     // (6, 128)
    gemm_bias_mma<<<ggrid, 256>>>(X1b, Wqt, bq, Qp);
    gemm_bias_mma<<<ggrid, 256>>>(X2b, Wkt, bk, Kp);

    dim3 agrid(SEQ / 128, BATCH, 2);       // (16, 8, 2)
    attn_mma<<<agrid, 256>>>(Qp, Kp, gnum, gden);

    finalize<<<BATCH*SEQ/256, 256>>>(gnum, gden, out);
}